// round 4
// baseline (speedup 1.0000x reference)
#include <cuda_runtime.h>
#include <cstdint>

#define N_NODES 100000
#define E_EDGES 3200000
#define IN_DIM  256
#define OUT_DIM 64
#define LN_EPS  1e-5f
#define NEG_SLOPE 0.01f

// Scratch (no allocation allowed in kernel_launch; use __device__ globals)
__device__ float g_deg[N_NODES];
__device__ float g_dinv[N_NODES];
__device__ float g_h[(size_t)N_NODES * OUT_DIM];

// ---------------------------------------------------------------------------
// 1) init deg with self-loop weight 1.0
__global__ __launch_bounds__(256) void k_init_deg() {
    int i = blockIdx.x * blockDim.x + threadIdx.x;
    if (i < N_NODES) g_deg[i] = 1.0f;
}

// 2) weighted degree over dst
__global__ __launch_bounds__(256) void k_deg(const int* __restrict__ ei,
                                             const float* __restrict__ ew) {
    int e = blockIdx.x * blockDim.x + threadIdx.x;
    if (e < E_EDGES) {
        int d = ei[E_EDGES + e];      // edge_index[1][e]
        atomicAdd(&g_deg[d], ew[e]);
    }
}

// 3) dinv = rsqrt(deg)  (deg >= 1 always due to self-loops)
__global__ __launch_bounds__(256) void k_dinv() {
    int i = blockIdx.x * blockDim.x + threadIdx.x;
    if (i < N_NODES) g_dinv[i] = rsqrtf(g_deg[i]);
}

// ---------------------------------------------------------------------------
// 4) GEMM: h = x @ W  [N,256]x[256,64]; also initializes agg (= d_out) with
//    the self-loop contribution h * dinv^2.
//    Block: 256 threads, 64-node tile. Each thread: 4 nodes x 4 cols.
#define TN 64
#define KC 16
__global__ __launch_bounds__(256) void k_gemm(const float* __restrict__ x,
                                              const float* __restrict__ W,
                                              float* __restrict__ agg) {
    __shared__ float xs[TN][KC + 1];
    __shared__ float ws[KC][OUT_DIM];

    int tid = threadIdx.x;
    int n0  = blockIdx.x * TN;
    int cg  = tid & 15;      // col group  -> cols [cg*4, cg*4+4)
    int ng  = tid >> 4;      // node group -> nodes [ng*4, ng*4+4)

    float acc[4][4];
#pragma unroll
    for (int a = 0; a < 4; a++)
#pragma unroll
        for (int j = 0; j < 4; j++) acc[a][j] = 0.0f;

    for (int k0 = 0; k0 < IN_DIM; k0 += KC) {
        // W chunk: KC x 64 = 1024 floats, coalesced
#pragma unroll
        for (int i = 0; i < 4; i++) {
            int idx = tid + i * 256;
            int kk = idx >> 6, j = idx & 63;
            ws[kk][j] = W[(k0 + kk) * OUT_DIM + j];
        }
        // x tile: 64 nodes x KC
#pragma unroll
        for (int i = 0; i < 4; i++) {
            int idx = tid + i * 256;
            int nn = idx >> 4, kk = idx & 15;
            int n = n0 + nn;
            xs[nn][kk] = (n < N_NODES) ? x[(size_t)n * IN_DIM + k0 + kk] : 0.0f;
        }
        __syncthreads();
#pragma unroll
        for (int kk = 0; kk < KC; kk++) {
            float wv[4];
#pragma unroll
            for (int j = 0; j < 4; j++) wv[j] = ws[kk][cg * 4 + j];
#pragma unroll
            for (int a = 0; a < 4; a++) {
                float xv = xs[ng * 4 + a][kk];
#pragma unroll
                for (int j = 0; j < 4; j++)
                    acc[a][j] = fmaf(xv, wv[j], acc[a][j]);
            }
        }
        __syncthreads();
    }

#pragma unroll
    for (int a = 0; a < 4; a++) {
        int n = n0 + ng * 4 + a;
        if (n < N_NODES) {
            float dv = g_dinv[n];
            float s  = dv * dv;          // self-loop norm
            size_t base = (size_t)n * OUT_DIM + cg * 4;
#pragma unroll
            for (int j = 0; j < 4; j++) {
                float hv = acc[a][j];
                g_h[base + j] = hv;
                agg[base + j] = hv * s;  // init agg with self-loop term
            }
        }
    }
}

// ---------------------------------------------------------------------------
// 5) Edge scatter: agg[dst] += h[src] * (dinv[src]*ew*dinv[dst])
//    16 threads per edge, float4 atomics (sm_90+).
__global__ __launch_bounds__(256) void k_scatter(const int* __restrict__ ei,
                                                 const float* __restrict__ ew,
                                                 float* __restrict__ agg) {
    long long t = (long long)blockIdx.x * blockDim.x + threadIdx.x;
    int e    = (int)(t >> 4);
    int lane = (int)(t & 15);
    if (e >= E_EDGES) return;

    int s = ei[e];
    int d = ei[E_EDGES + e];
    float norm = g_dinv[s] * ew[e] * g_dinv[d];

    const float4* hp = reinterpret_cast<const float4*>(g_h + (size_t)s * OUT_DIM);
    float4 hv = hp[lane];
    float4 v  = make_float4(hv.x * norm, hv.y * norm, hv.z * norm, hv.w * norm);

    float4* ap = reinterpret_cast<float4*>(agg + (size_t)d * OUT_DIM) + lane;
    atomicAdd(ap, v);   // vector fp32 atomic (compute capability >= 9.0)
}

// ---------------------------------------------------------------------------
// 6) Epilogue: y = agg + b, leaky-relu, LayerNorm(gamma, beta). Warp per node.
__global__ __launch_bounds__(256) void k_epilogue(float* __restrict__ out,
                                                  const float* __restrict__ b,
                                                  const float* __restrict__ gamma,
                                                  const float* __restrict__ beta) {
    long long t = (long long)blockIdx.x * blockDim.x + threadIdx.x;
    int node = (int)(t >> 5);
    int lane = (int)(t & 31);
    if (node >= N_NODES) return;

    float* row = out + (size_t)node * OUT_DIM;
    float v0 = row[lane]      + b[lane];
    float v1 = row[lane + 32] + b[lane + 32];
    v0 = (v0 >= 0.0f) ? v0 : NEG_SLOPE * v0;
    v1 = (v1 >= 0.0f) ? v1 : NEG_SLOPE * v1;

    float sum = v0 + v1;
#pragma unroll
    for (int o = 16; o > 0; o >>= 1) sum += __shfl_xor_sync(0xFFFFFFFFu, sum, o);
    float mu = sum * (1.0f / OUT_DIM);

    float d0 = v0 - mu, d1 = v1 - mu;
    float sq = d0 * d0 + d1 * d1;
#pragma unroll
    for (int o = 16; o > 0; o >>= 1) sq += __shfl_xor_sync(0xFFFFFFFFu, sq, o);
    float inv = rsqrtf(sq * (1.0f / OUT_DIM) + LN_EPS);

    row[lane]      = d0 * inv * gamma[lane]      + beta[lane];
    row[lane + 32] = d1 * inv * gamma[lane + 32] + beta[lane + 32];
}

// ---------------------------------------------------------------------------
extern "C" void kernel_launch(void* const* d_in, const int* in_sizes, int n_in,
                              void* d_out, int out_size) {
    const float* x     = (const float*)d_in[0];
    const int*   ei    = (const int*)  d_in[1];
    const float* ew    = (const float*)d_in[2];
    const float* W     = (const float*)d_in[3];
    const float* b     = (const float*)d_in[4];
    const float* gamma = (const float*)d_in[5];
    const float* beta  = (const float*)d_in[6];
    float* out = (float*)d_out;

    k_init_deg<<<(N_NODES + 255) / 256, 256>>>();
    k_deg<<<(E_EDGES + 255) / 256, 256>>>(ei, ew);
    k_dinv<<<(N_NODES + 255) / 256, 256>>>();
    k_gemm<<<(N_NODES + TN - 1) / TN, 256>>>(x, W, out);
    {
        long long total = (long long)E_EDGES * 16;
        int blocks = (int)((total + 255) / 256);
        k_scatter<<<blocks, 256>>>(ei, ew, out);
    }
    {
        long long total = (long long)N_NODES * 32;
        int blocks = (int)((total + 255) / 256);
        k_epilogue<<<blocks, 256>>>(out, b, gamma, beta);
    }
}

// round 7
// speedup vs baseline: 1.0657x; 1.0657x over previous
#include <cuda_runtime.h>
#include <cstdint>

#define N_NODES 100000
#define E_EDGES 3200000
#define IN_DIM  256
#define OUT_DIM 64
#define LN_EPS  1e-5f
#define NEG_SLOPE 0.01f

// ---------------------------------------------------------------------------
// Scratch (__device__ globals; no allocation allowed)
__device__ float g_deg [N_NODES];
__device__ float g_dinv[N_NODES];
__device__ float g_h   [(size_t)N_NODES * OUT_DIM];
__device__ int   g_cnt [N_NODES];          // edge count per dst (no self-loop)
__device__ int   g_off [N_NODES];          // CSR slot start per dst (unordered)
__device__ int   g_cur [N_NODES];          // fill cursor
__device__ int2  g_pack[E_EDGES];          // (src, __float_as_int(norm))
__device__ int   g_total;

// ---------------------------------------------------------------------------
// f32x2 packed-FMA helpers (PTX-only FFMA2)
__device__ __forceinline__ unsigned long long f2_rep(float a) {
    unsigned long long r;
    asm("mov.b64 %0, {%1, %1};" : "=l"(r) : "f"(a));
    return r;
}
__device__ __forceinline__ unsigned long long ffma2(unsigned long long a,
                                                    unsigned long long b,
                                                    unsigned long long c) {
    unsigned long long d;
    asm("fma.rn.f32x2 %0, %1, %2, %3;" : "=l"(d) : "l"(a), "l"(b), "l"(c));
    return d;
}
__device__ __forceinline__ void f2_unpack(unsigned long long v, float& lo, float& hi) {
    asm("mov.b64 {%0, %1}, %2;" : "=f"(lo), "=f"(hi) : "l"(v));
}

// ---------------------------------------------------------------------------
// 1) init: deg = 1 (self-loop weight), cnt = 0, total = 0
__global__ __launch_bounds__(256) void k_init() {
    int i = blockIdx.x * blockDim.x + threadIdx.x;
    if (i < N_NODES) { g_deg[i] = 1.0f; g_cnt[i] = 0; }
    if (i == 0) g_total = 0;
}

// 2) weighted degree + histogram over dst
__global__ __launch_bounds__(256) void k_deg(const int* __restrict__ ei,
                                             const float* __restrict__ ew) {
    int e = blockIdx.x * blockDim.x + threadIdx.x;
    if (e < E_EDGES) {
        int d = ei[E_EDGES + e];
        atomicAdd(&g_deg[d], ew[e]);
        atomicAdd(&g_cnt[d], 1);
    }
}

// 3) dinv = rsqrt(deg)   (deg >= 1 due to self-loop)
__global__ __launch_bounds__(256) void k_dinv() {
    int i = blockIdx.x * blockDim.x + threadIdx.x;
    if (i < N_NODES) g_dinv[i] = rsqrtf(g_deg[i]);
}

// 4) slot allocation: block-local exclusive scan + one global atomic per block.
//    Node ordering in slot space is arbitrary — only contiguity per node matters.
__global__ __launch_bounds__(1024) void k_alloc() {
    __shared__ int sdata[1024];
    __shared__ int sbase;
    int tid = threadIdx.x;
    int i = blockIdx.x * 1024 + tid;
    int c = (i < N_NODES) ? g_cnt[i] : 0;
    sdata[tid] = c;
    __syncthreads();
#pragma unroll
    for (int o = 1; o < 1024; o <<= 1) {
        int v = (tid >= o) ? sdata[tid - o] : 0;
        __syncthreads();
        sdata[tid] += v;
        __syncthreads();
    }
    if (tid == 1023) sbase = atomicAdd(&g_total, sdata[1023]);
    __syncthreads();
    if (i < N_NODES) {
        int start = sbase + sdata[tid] - c;   // exclusive scan
        g_off[i] = start;
        g_cur[i] = start;
    }
}

// 5) fill CSR: pack (src, norm) per edge into dst's slot range
__global__ __launch_bounds__(256) void k_fill(const int* __restrict__ ei,
                                              const float* __restrict__ ew) {
    int e = blockIdx.x * blockDim.x + threadIdx.x;
    if (e < E_EDGES) {
        int s = ei[e];
        int d = ei[E_EDGES + e];
        float nm = g_dinv[s] * ew[e] * g_dinv[d];
        int pos = atomicAdd(&g_cur[d], 1);
        g_pack[pos] = make_int2(s, __float_as_int(nm));
    }
}

// ---------------------------------------------------------------------------
// 6) GEMM: h = x @ W  with packed f32x2 FMAs.
//    Block 256 thr, 128-node tile; thread tile = 4 nodes x 8 cols (4x4 f32x2).
#define TN 128
#define KC 16
__global__ __launch_bounds__(256) void k_gemm(const float* __restrict__ x,
                                              const float* __restrict__ W) {
    __shared__ __align__(16) float xs[TN][20];     // pad: stride 80B, 16B-aligned
    __shared__ __align__(16) float ws[KC][OUT_DIM];

    int tid = threadIdx.x;
    int n0  = blockIdx.x * TN;
    int cg  = tid & 7;       // cols [cg*8, cg*8+8)
    int ng  = tid >> 3;      // nodes [ng*4, ng*4+4)

    unsigned long long acc[4][4];
#pragma unroll
    for (int a = 0; a < 4; a++)
#pragma unroll
        for (int j = 0; j < 4; j++) acc[a][j] = 0ull;   // (0.0f, 0.0f)

    for (int k0 = 0; k0 < IN_DIM; k0 += KC) {
        // W chunk: 16x64 floats, coalesced
#pragma unroll
        for (int i = 0; i < 4; i++) {
            int idx = tid + i * 256;
            int kk = idx >> 6, j = idx & 63;
            ws[kk][j] = W[(k0 + kk) * OUT_DIM + j];
        }
        // x tile: 128 nodes x 16, float4 loads
#pragma unroll
        for (int i = 0; i < 2; i++) {
            int idx = tid + i * 256;
            int nn = idx >> 2, kq = idx & 3;
            int n  = n0 + nn;
            float4 v = (n < N_NODES)
                ? *reinterpret_cast<const float4*>(x + (size_t)n * IN_DIM + k0 + kq * 4)
                : make_float4(0.f, 0.f, 0.f, 0.f);
            *reinterpret_cast<float4*>(&xs[nn][kq * 4]) = v;
        }
        __syncthreads();
#pragma unroll
        for (int kk = 0; kk < KC; kk++) {
            unsigned long long xv2[4];
#pragma unroll
            for (int a = 0; a < 4; a++)
                xv2[a] = f2_rep(xs[ng * 4 + a][kk]);
            unsigned long long wv2[4];
#pragma unroll
            for (int j = 0; j < 4; j++)
                wv2[j] = *reinterpret_cast<const unsigned long long*>(&ws[kk][cg * 8 + j * 2]);
#pragma unroll
            for (int a = 0; a < 4; a++)
#pragma unroll
                for (int j = 0; j < 4; j++)
                    acc[a][j] = ffma2(xv2[a], wv2[j], acc[a][j]);
        }
        __syncthreads();
    }

#pragma unroll
    for (int a = 0; a < 4; a++) {
        int n = n0 + ng * 4 + a;
        if (n < N_NODES) {
            float o[8];
#pragma unroll
            for (int j = 0; j < 4; j++) f2_unpack(acc[a][j], o[j * 2], o[j * 2 + 1]);
            float* dst = g_h + (size_t)n * OUT_DIM + cg * 8;
            *reinterpret_cast<float4*>(dst)     = make_float4(o[0], o[1], o[2], o[3]);
            *reinterpret_cast<float4*>(dst + 4) = make_float4(o[4], o[5], o[6], o[7]);
        }
    }
}

// ---------------------------------------------------------------------------
// 7) Fused gather + bias + leaky-relu + LayerNorm.
//    One warp per dst node, 2 cols per lane, NO atomics.
__global__ __launch_bounds__(256) void k_gather_ln(float* __restrict__ out,
                                                   const float* __restrict__ b,
                                                   const float* __restrict__ gamma,
                                                   const float* __restrict__ beta) {
    int gt   = blockIdx.x * blockDim.x + threadIdx.x;
    int node = gt >> 5;
    int lane = gt & 31;
    if (node >= N_NODES) return;

    // self-loop contribution: h[n] * dinv[n]^2
    float dv = g_dinv[node];
    float s  = dv * dv;
    float2 hv = *reinterpret_cast<const float2*>(g_h + (size_t)node * OUT_DIM + lane * 2);
    float accx = hv.x * s, accy = hv.y * s;

    int start = g_off[node];
    int deg   = g_cnt[node];
    const int2* pp = g_pack + start;

    int i = 0;
    for (; i + 4 <= deg; i += 4) {
        int2 p0 = pp[i], p1 = pp[i + 1], p2 = pp[i + 2], p3 = pp[i + 3];
        float2 h0 = *reinterpret_cast<const float2*>(g_h + (size_t)p0.x * OUT_DIM + lane * 2);
        float2 h1 = *reinterpret_cast<const float2*>(g_h + (size_t)p1.x * OUT_DIM + lane * 2);
        float2 h2 = *reinterpret_cast<const float2*>(g_h + (size_t)p2.x * OUT_DIM + lane * 2);
        float2 h3 = *reinterpret_cast<const float2*>(g_h + (size_t)p3.x * OUT_DIM + lane * 2);
        float n0 = __int_as_float(p0.y), n1 = __int_as_float(p1.y);
        float n2 = __int_as_float(p2.y), n3 = __int_as_float(p3.y);
        accx = fmaf(h0.x, n0, accx); accy = fmaf(h0.y, n0, accy);
        accx = fmaf(h1.x, n1, accx); accy = fmaf(h1.y, n1, accy);
        accx = fmaf(h2.x, n2, accx); accy = fmaf(h2.y, n2, accy);
        accx = fmaf(h3.x, n3, accx); accy = fmaf(h3.y, n3, accy);
    }
    for (; i < deg; i++) {
        int2 p = pp[i];
        float2 h = *reinterpret_cast<const float2*>(g_h + (size_t)p.x * OUT_DIM + lane * 2);
        float nm = __int_as_float(p.y);
        accx = fmaf(h.x, nm, accx); accy = fmaf(h.y, nm, accy);
    }

    // bias + leaky relu
    float2 bb = *reinterpret_cast<const float2*>(b + lane * 2);
    float y0 = accx + bb.x;
    float y1 = accy + bb.y;
    y0 = (y0 >= 0.0f) ? y0 : NEG_SLOPE * y0;
    y1 = (y1 >= 0.0f) ? y1 : NEG_SLOPE * y1;

    // LayerNorm over 64 cols (2 per lane)
    float sum = y0 + y1;
#pragma unroll
    for (int o = 16; o > 0; o >>= 1) sum += __shfl_xor_sync(0xFFFFFFFFu, sum, o);
    float mu = sum * (1.0f / OUT_DIM);

    float d0 = y0 - mu, d1 = y1 - mu;
    float sq = d0 * d0 + d1 * d1;
#pragma unroll
    for (int o = 16; o > 0; o >>= 1) sq += __shfl_xor_sync(0xFFFFFFFFu, sq, o);
    float inv = rsqrtf(sq * (1.0f / OUT_DIM) + LN_EPS);

    float2 gg = *reinterpret_cast<const float2*>(gamma + lane * 2);
    float2 be = *reinterpret_cast<const float2*>(beta  + lane * 2);
    float2 res = make_float2(d0 * inv * gg.x + be.x, d1 * inv * gg.y + be.y);
    *reinterpret_cast<float2*>(out + (size_t)node * OUT_DIM + lane * 2) = res;
}

// ---------------------------------------------------------------------------
extern "C" void kernel_launch(void* const* d_in, const int* in_sizes, int n_in,
                              void* d_out, int out_size) {
    const float* x     = (const float*)d_in[0];
    const int*   ei    = (const int*)  d_in[1];
    const float* ew    = (const float*)d_in[2];
    const float* W     = (const float*)d_in[3];
    const float* b     = (const float*)d_in[4];
    const float* gamma = (const float*)d_in[5];
    const float* beta  = (const float*)d_in[6];
    float* out = (float*)d_out;

    k_init<<<(N_NODES + 255) / 256, 256>>>();
    k_deg<<<(E_EDGES + 255) / 256, 256>>>(ei, ew);
    k_dinv<<<(N_NODES + 255) / 256, 256>>>();
    k_alloc<<<(N_NODES + 1023) / 1024, 1024>>>();
    k_fill<<<(E_EDGES + 255) / 256, 256>>>(ei, ew);
    k_gemm<<<(N_NODES + TN - 1) / TN, 256>>>(x, W);
    {
        long long total = (long long)N_NODES * 32;
        int blocks = (int)((total + 255) / 256);
        k_gather_ln<<<blocks, 256>>>(out, b, gamma, beta);
    }
}